// round 5
// baseline (speedup 1.0000x reference)
#include <cuda_runtime.h>
#include <math.h>
#include <stdint.h>

// Problem dims (fixed by the dataset)
#define B_ROWS 65536
#define K_DIM  1024
#define N_INF  1024
#define E_DIM  256

// ---------------- static device scratch (no allocations allowed) ----------------
__device__ float g_logits[(size_t)B_ROWS * K_DIM];   // 256 MB: logits + gumbel + bias
__device__ float g_part[512 * K_DIM];                // per-CTA avg_p partial sums (2 MB)

// ---------------- f32x2 helpers (Blackwell packed fp32 pipe) ----------------
__device__ __forceinline__ unsigned long long pack_dup(float a) {
    unsigned long long r;
    unsigned int ai = __float_as_uint(a);
    asm("mov.b64 %0, {%1, %1};" : "=l"(r) : "r"(ai));
    return r;
}
__device__ __forceinline__ void ffma2(unsigned long long& d,
                                      unsigned long long a,
                                      unsigned long long b) {
    asm("fma.rn.f32x2 %0, %1, %2, %0;" : "+l"(d) : "l"(a), "l"(b));
}
__device__ __forceinline__ float2 unpack2(unsigned long long v) {
    unsigned int lo, hi;
    asm("mov.b64 {%0, %1}, %2;" : "=r"(lo), "=r"(hi) : "l"(v));
    return make_float2(__uint_as_float(lo), __uint_as_float(hi));
}

// ---------------- Pass 1: fp32 GEMM  t = x @ W^T + b + gumbel ----------------
#define BM 128
#define BN 128
#define BK 16
#define TM 16
#define TN 8
#define SA_STRIDE 132   // pad: 132*4B = 528B, 16B-aligned rows, halves STS conflicts

__device__ __forceinline__ void ldg_tile(const float* __restrict__ base,
                                         int tid, int k0, float4 r[4]) {
#pragma unroll
    for (int t = 0; t < 4; t++) {
        int f4 = tid + t * 128;
        int rr = f4 >> 2, c4 = f4 & 3;
        r[t] = *(const float4*)(base + (size_t)rr * N_INF + k0 + c4 * 4);
    }
}
__device__ __forceinline__ void sts_tile(float* s, int tid, const float4 r[4]) {
#pragma unroll
    for (int t = 0; t < 4; t++) {
        int f4 = tid + t * 128;
        int rr = f4 >> 2, c4 = f4 & 3;
        s[(c4 * 4 + 0) * SA_STRIDE + rr] = r[t].x;
        s[(c4 * 4 + 1) * SA_STRIDE + rr] = r[t].y;
        s[(c4 * 4 + 2) * SA_STRIDE + rr] = r[t].z;
        s[(c4 * 4 + 3) * SA_STRIDE + rr] = r[t].w;
    }
}

__global__ void __launch_bounds__(128, 2)
gemm_kernel(const float* __restrict__ x, const float* __restrict__ W,
            const float* __restrict__ b_enc, const float* __restrict__ gumbel)
{
    __shared__ float sA[2][BK * SA_STRIDE];
    __shared__ float sB[2][BK * SA_STRIDE];

    const int tid = threadIdx.x;
    const int rowBase = blockIdx.y * BM;
    const int colBase = blockIdx.x * BN;
    const int tx = tid & 15, ty = tid >> 4;
    const int row0 = ty * TM;   // 0..112
    const int col0 = tx * TN;   // 0..120

    const float* aBase = x + (size_t)rowBase * N_INF;
    const float* bBase = W + (size_t)colBase * N_INF;

    unsigned long long acc[TM][TN / 2];
#pragma unroll
    for (int i = 0; i < TM; i++)
#pragma unroll
        for (int j = 0; j < TN / 2; j++) acc[i][j] = 0ULL;

    float4 ra[4], rb[4];
    ldg_tile(aBase, tid, 0, ra);
    ldg_tile(bBase, tid, 0, rb);
    sts_tile(sA[0], tid, ra);
    sts_tile(sB[0], tid, rb);
    __syncthreads();

    const int NT = N_INF / BK; // 64
    for (int kt = 0; kt < NT; kt++) {
        int buf = kt & 1;
        if (kt + 1 < NT) {
            ldg_tile(aBase, tid, (kt + 1) * BK, ra);
            ldg_tile(bBase, tid, (kt + 1) * BK, rb);
        }
        const float* sa = sA[buf];
        const float* sb = sB[buf];
#pragma unroll
        for (int k = 0; k < BK; k++) {
            const float* pa = sa + k * SA_STRIDE + row0;
            float4 a0 = *(const float4*)(pa + 0);
            float4 a1 = *(const float4*)(pa + 4);
            float4 a2 = *(const float4*)(pa + 8);
            float4 a3 = *(const float4*)(pa + 12);
            const float* pb = sb + k * SA_STRIDE + col0;
            ulonglong2 b01 = *(const ulonglong2*)(pb + 0);
            ulonglong2 b23 = *(const ulonglong2*)(pb + 4);
            unsigned long long bb0 = b01.x, bb1 = b01.y, bb2 = b23.x, bb3 = b23.y;
            float av[16] = {a0.x, a0.y, a0.z, a0.w, a1.x, a1.y, a1.z, a1.w,
                            a2.x, a2.y, a2.z, a2.w, a3.x, a3.y, a3.z, a3.w};
#pragma unroll
            for (int i = 0; i < TM; i++) {
                unsigned long long ad = pack_dup(av[i]);
                ffma2(acc[i][0], ad, bb0);
                ffma2(acc[i][1], ad, bb1);
                ffma2(acc[i][2], ad, bb2);
                ffma2(acc[i][3], ad, bb3);
            }
        }
        if (kt + 1 < NT) {
            sts_tile(sA[buf ^ 1], tid, ra);
            sts_tile(sB[buf ^ 1], tid, rb);
            __syncthreads();
        }
    }

    // epilogue: += bias + gumbel, store to g_logits
    float bv[8];
#pragma unroll
    for (int j = 0; j < 8; j++) bv[j] = __ldg(&b_enc[colBase + col0 + j]);

#pragma unroll
    for (int i = 0; i < TM; i++) {
        size_t row = (size_t)(rowBase + row0 + i);
        size_t off = row * K_DIM + colBase + col0;
        float4 g0 = *(const float4*)&gumbel[off];
        float4 g1 = *(const float4*)&gumbel[off + 4];
        float2 p0 = unpack2(acc[i][0]);
        float2 p1 = unpack2(acc[i][1]);
        float2 p2 = unpack2(acc[i][2]);
        float2 p3 = unpack2(acc[i][3]);
        float4 o0 = make_float4(p0.x + bv[0] + g0.x, p0.y + bv[1] + g0.y,
                                p1.x + bv[2] + g0.z, p1.y + bv[3] + g0.w);
        float4 o1 = make_float4(p2.x + bv[4] + g1.x, p2.y + bv[5] + g1.y,
                                p3.x + bv[6] + g1.z, p3.y + bv[7] + g1.w);
        *(float4*)&g_logits[off] = o0;
        *(float4*)&g_logits[off + 4] = o1;
    }
}

// ---------------- Pass 2: per-row argmax/softmax, z_q gather, avg_p partials ----------------
// 512 CTAs x 8 warps x 16 rows = 65536 rows. Each lane owns a fixed set of 32 k-slots,
// so avg_p accumulation is register-resident and fully deterministic (no atomics).
#define ROWS_PER_WARP 16

__global__ void __launch_bounds__(256)
rowpass_kernel(const float* __restrict__ codebook, float* __restrict__ out,
               long long out_size)
{
    __shared__ float sPart[8 * K_DIM]; // 32 KB
    const int tid = threadIdx.x;
    const int lane = tid & 31;
    const int warp = tid >> 5;

    float priv[32];
#pragma unroll
    for (int i = 0; i < 32; i++) priv[i] = 0.f;

    const size_t Z = (size_t)B_ROWS * E_DIM;
    const int rowStart = (blockIdx.x * 8 + warp) * ROWS_PER_WARP;

    for (int r = 0; r < ROWS_PER_WARP; r++) {
        const int row = rowStart + r;
        const float* lp = &g_logits[(size_t)row * K_DIM];
        float4 v[8];
#pragma unroll
        for (int i = 0; i < 8; i++)
            v[i] = *(const float4*)&lp[i * 128 + lane * 4];

        // local max/argmax, first-occurrence semantics (k ascending per lane)
        float bvv = -INFINITY;
        int bk = 0;
#pragma unroll
        for (int i = 0; i < 8; i++) {
            const int kb = i * 128 + lane * 4;
            float* f = (float*)&v[i];
#pragma unroll
            for (int c = 0; c < 4; c++) {
                if (f[c] > bvv) { bvv = f[c]; bk = kb + c; }
            }
        }
        // cross-lane reduce (max, argmin-on-tie) — associative & commutative
#pragma unroll
        for (int off = 16; off; off >>= 1) {
            float ov = __shfl_xor_sync(0xffffffffu, bvv, off);
            int   ok = __shfl_xor_sync(0xffffffffu, bk, off);
            if (ov > bvv || (ov == bvv && ok < bk)) { bvv = ov; bk = ok; }
        }

        // exp + row sum
        float s = 0.f;
#pragma unroll
        for (int i = 0; i < 8; i++) {
            float* f = (float*)&v[i];
#pragma unroll
            for (int c = 0; c < 4; c++) {
                f[c] = expf(f[c] - bvv);
                s += f[c];
            }
        }
#pragma unroll
        for (int off = 16; off; off >>= 1)
            s += __shfl_xor_sync(0xffffffffu, s, off);
        const float inv = 1.f / s;

        // accumulate soft into lane-private avg_p bins
#pragma unroll
        for (int i = 0; i < 8; i++) {
            float* f = (float*)&v[i];
#pragma unroll
            for (int c = 0; c < 4; c++) priv[i * 4 + c] += f[c] * inv;
        }

        // m output (cast to float, exact for 0..1023)
        if (lane == 0) {
            size_t mi = Z + (size_t)row;
            if (mi < (size_t)out_size) out[mi] = (float)bk;
        }
        // z_q = codebook[bk, :]  (codebook is 1 MB -> L2 resident)
        const float* cbp = &codebook[(size_t)bk * E_DIM];
        float* zo = &out[(size_t)row * E_DIM];
#pragma unroll
        for (int i = 0; i < 2; i++) {
            float4 cv = *(const float4*)&cbp[i * 128 + lane * 4];
            *(float4*)&zo[i * 128 + lane * 4] = cv;
        }
    }

    // warp-private bins -> shared (unique slots, no atomics)
#pragma unroll
    for (int i = 0; i < 8; i++)
#pragma unroll
        for (int c = 0; c < 4; c++)
            sPart[warp * K_DIM + i * 128 + lane * 4 + c] = priv[i * 4 + c];
    __syncthreads();

    // fixed-order reduce of the 8 warps -> per-CTA partial
    for (int k = tid; k < K_DIM; k += 256) {
        float sum = 0.f;
#pragma unroll
        for (int w = 0; w < 8; w++) sum += sPart[w * K_DIM + k];
        g_part[(size_t)blockIdx.x * K_DIM + k] = sum;
    }
}

// ---------------- Pass 3: diversity scalar + trailing zero ----------------
__global__ void __launch_bounds__(1024)
finalize_kernel(float* __restrict__ out, long long out_size)
{
    __shared__ double sred[32];
    const int tid = threadIdx.x; // 1024 threads, one k each
    double part = 0.0;
    {
        const int k = tid;
        float sum = 0.f;
        for (int c = 0; c < 512; c++) sum += g_part[(size_t)c * K_DIM + k];
        double avg = (double)sum / (double)B_ROWS;
        double a = avg < 1e-9 ? 1e-9 : avg;
        part = avg * (log(a) + log((double)K_DIM));
    }
#pragma unroll
    for (int off = 16; off; off >>= 1)
        part += __shfl_xor_sync(0xffffffffu, part, off);
    if ((tid & 31) == 0) sred[tid >> 5] = part;
    __syncthreads();
    if (tid < 32) {
        double v = sred[tid];
#pragma unroll
        for (int off = 16; off; off >>= 1)
            v += __shfl_xor_sync(0xffffffffu, v, off);
        if (tid == 0) {
            size_t di = (size_t)B_ROWS * E_DIM + B_ROWS;
            if ((long long)di < out_size) out[di] = (float)v;
            if ((long long)(di + 1) < out_size) out[di + 1] = 0.f;
        }
    }
}

// ---------------- launch ----------------
extern "C" void kernel_launch(void* const* d_in, const int* in_sizes, int n_in,
                              void* d_out, int out_size)
{
    const float* x       = (const float*)d_in[0]; // [B, n_in]
    const float* gumbel  = (const float*)d_in[1]; // [B, K]
    const float* W_enc   = (const float*)d_in[2]; // [K, n_in]
    const float* b_enc   = (const float*)d_in[3]; // [K]
    const float* codebook= (const float*)d_in[4]; // [K, E]
    float* out = (float*)d_out;

    dim3 g1(K_DIM / BN, B_ROWS / BM); // (8, 512)
    gemm_kernel<<<g1, 128>>>(x, W_enc, b_enc, gumbel);
    rowpass_kernel<<<512, 256>>>(codebook, out, (long long)out_size);
    finalize_kernel<<<1, 1024>>>(out, (long long)out_size);
}

// round 6
// speedup vs baseline: 1.0007x; 1.0007x over previous
#include <cuda_runtime.h>
#include <math.h>
#include <stdint.h>

// Problem dims (fixed by the dataset)
#define B_ROWS 65536
#define K_DIM  1024
#define N_INF  1024
#define E_DIM  256

// ---------------- static device scratch (no allocations allowed) ----------------
__device__ float g_logits[(size_t)B_ROWS * K_DIM];   // 256 MB: logits + gumbel + bias
__device__ float g_part[512 * K_DIM];                // per-CTA avg_p partial sums (2 MB)

// ---------------- f32x2 helpers (Blackwell packed fp32 pipe) ----------------
__device__ __forceinline__ unsigned long long pack_dup(float a) {
    unsigned long long r;
    unsigned int ai = __float_as_uint(a);
    asm("mov.b64 %0, {%1, %1};" : "=l"(r) : "r"(ai));
    return r;
}
__device__ __forceinline__ void ffma2(unsigned long long& d,
                                      unsigned long long a,
                                      unsigned long long b) {
    asm("fma.rn.f32x2 %0, %1, %2, %0;" : "+l"(d) : "l"(a), "l"(b));
}
__device__ __forceinline__ float2 unpack2(unsigned long long v) {
    unsigned int lo, hi;
    asm("mov.b64 {%0, %1}, %2;" : "=r"(lo), "=r"(hi) : "l"(v));
    return make_float2(__uint_as_float(lo), __uint_as_float(hi));
}

// ---------------- Pass 1: fp32 GEMM  t = x @ W^T + b + gumbel ----------------
#define BM 128
#define BN 128
#define BK 16
#define TM 16
#define TN 8
#define SA_STRIDE 132   // pad: 132*4B = 528B, 16B-aligned rows, halves STS conflicts

__device__ __forceinline__ void ldg_tile(const float* __restrict__ base,
                                         int tid, int k0, float4 r[4]) {
#pragma unroll
    for (int t = 0; t < 4; t++) {
        int f4 = tid + t * 128;
        int rr = f4 >> 2, c4 = f4 & 3;
        r[t] = *(const float4*)(base + (size_t)rr * N_INF + k0 + c4 * 4);
    }
}
__device__ __forceinline__ void sts_tile(float* s, int tid, const float4 r[4]) {
#pragma unroll
    for (int t = 0; t < 4; t++) {
        int f4 = tid + t * 128;
        int rr = f4 >> 2, c4 = f4 & 3;
        s[(c4 * 4 + 0) * SA_STRIDE + rr] = r[t].x;
        s[(c4 * 4 + 1) * SA_STRIDE + rr] = r[t].y;
        s[(c4 * 4 + 2) * SA_STRIDE + rr] = r[t].z;
        s[(c4 * 4 + 3) * SA_STRIDE + rr] = r[t].w;
    }
}

__global__ void __launch_bounds__(128, 2)
gemm_kernel(const float* __restrict__ x, const float* __restrict__ W,
            const float* __restrict__ b_enc, const float* __restrict__ gumbel)
{
    __shared__ float sA[2][BK * SA_STRIDE];
    __shared__ float sB[2][BK * SA_STRIDE];

    const int tid = threadIdx.x;
    const int rowBase = blockIdx.y * BM;
    const int colBase = blockIdx.x * BN;
    const int tx = tid & 15, ty = tid >> 4;
    const int row0 = ty * TM;   // 0..112
    const int col0 = tx * TN;   // 0..120

    const float* aBase = x + (size_t)rowBase * N_INF;
    const float* bBase = W + (size_t)colBase * N_INF;

    unsigned long long acc[TM][TN / 2];
#pragma unroll
    for (int i = 0; i < TM; i++)
#pragma unroll
        for (int j = 0; j < TN / 2; j++) acc[i][j] = 0ULL;

    float4 ra[4], rb[4];
    ldg_tile(aBase, tid, 0, ra);
    ldg_tile(bBase, tid, 0, rb);
    sts_tile(sA[0], tid, ra);
    sts_tile(sB[0], tid, rb);
    __syncthreads();

    const int NT = N_INF / BK; // 64
    for (int kt = 0; kt < NT; kt++) {
        int buf = kt & 1;
        if (kt + 1 < NT) {
            ldg_tile(aBase, tid, (kt + 1) * BK, ra);
            ldg_tile(bBase, tid, (kt + 1) * BK, rb);
        }
        const float* sa = sA[buf];
        const float* sb = sB[buf];
#pragma unroll
        for (int k = 0; k < BK; k++) {
            const float* pa = sa + k * SA_STRIDE + row0;
            float4 a0 = *(const float4*)(pa + 0);
            float4 a1 = *(const float4*)(pa + 4);
            float4 a2 = *(const float4*)(pa + 8);
            float4 a3 = *(const float4*)(pa + 12);
            const float* pb = sb + k * SA_STRIDE + col0;
            ulonglong2 b01 = *(const ulonglong2*)(pb + 0);
            ulonglong2 b23 = *(const ulonglong2*)(pb + 4);
            unsigned long long bb0 = b01.x, bb1 = b01.y, bb2 = b23.x, bb3 = b23.y;
            float av[16] = {a0.x, a0.y, a0.z, a0.w, a1.x, a1.y, a1.z, a1.w,
                            a2.x, a2.y, a2.z, a2.w, a3.x, a3.y, a3.z, a3.w};
#pragma unroll
            for (int i = 0; i < TM; i++) {
                unsigned long long ad = pack_dup(av[i]);
                ffma2(acc[i][0], ad, bb0);
                ffma2(acc[i][1], ad, bb1);
                ffma2(acc[i][2], ad, bb2);
                ffma2(acc[i][3], ad, bb3);
            }
        }
        if (kt + 1 < NT) {
            sts_tile(sA[buf ^ 1], tid, ra);
            sts_tile(sB[buf ^ 1], tid, rb);
            __syncthreads();
        }
    }

    // epilogue: += bias + gumbel, store to g_logits
    float bv[8];
#pragma unroll
    for (int j = 0; j < 8; j++) bv[j] = __ldg(&b_enc[colBase + col0 + j]);

#pragma unroll
    for (int i = 0; i < TM; i++) {
        size_t row = (size_t)(rowBase + row0 + i);
        size_t off = row * K_DIM + colBase + col0;
        float4 g0 = *(const float4*)&gumbel[off];
        float4 g1 = *(const float4*)&gumbel[off + 4];
        float2 p0 = unpack2(acc[i][0]);
        float2 p1 = unpack2(acc[i][1]);
        float2 p2 = unpack2(acc[i][2]);
        float2 p3 = unpack2(acc[i][3]);
        float4 o0 = make_float4(p0.x + bv[0] + g0.x, p0.y + bv[1] + g0.y,
                                p1.x + bv[2] + g0.z, p1.y + bv[3] + g0.w);
        float4 o1 = make_float4(p2.x + bv[4] + g1.x, p2.y + bv[5] + g1.y,
                                p3.x + bv[6] + g1.z, p3.y + bv[7] + g1.w);
        *(float4*)&g_logits[off] = o0;
        *(float4*)&g_logits[off + 4] = o1;
    }
}

// ---------------- Pass 2: per-row argmax/softmax, z_q gather, avg_p partials ----------------
// 512 CTAs x 8 warps x 16 rows = 65536 rows. Each lane owns a fixed set of 32 k-slots,
// so avg_p accumulation is register-resident and fully deterministic (no atomics).
#define ROWS_PER_WARP 16

__global__ void __launch_bounds__(256)
rowpass_kernel(const float* __restrict__ codebook, float* __restrict__ out,
               long long out_size)
{
    __shared__ float sPart[8 * K_DIM]; // 32 KB
    const int tid = threadIdx.x;
    const int lane = tid & 31;
    const int warp = tid >> 5;

    float priv[32];
#pragma unroll
    for (int i = 0; i < 32; i++) priv[i] = 0.f;

    const size_t Z = (size_t)B_ROWS * E_DIM;
    const int rowStart = (blockIdx.x * 8 + warp) * ROWS_PER_WARP;

    for (int r = 0; r < ROWS_PER_WARP; r++) {
        const int row = rowStart + r;
        const float* lp = &g_logits[(size_t)row * K_DIM];
        float4 v[8];
#pragma unroll
        for (int i = 0; i < 8; i++)
            v[i] = *(const float4*)&lp[i * 128 + lane * 4];

        // local max/argmax, first-occurrence semantics (k ascending per lane)
        float bvv = -INFINITY;
        int bk = 0;
#pragma unroll
        for (int i = 0; i < 8; i++) {
            const int kb = i * 128 + lane * 4;
            float* f = (float*)&v[i];
#pragma unroll
            for (int c = 0; c < 4; c++) {
                if (f[c] > bvv) { bvv = f[c]; bk = kb + c; }
            }
        }
        // cross-lane reduce (max, argmin-on-tie) — associative & commutative
#pragma unroll
        for (int off = 16; off; off >>= 1) {
            float ov = __shfl_xor_sync(0xffffffffu, bvv, off);
            int   ok = __shfl_xor_sync(0xffffffffu, bk, off);
            if (ov > bvv || (ov == bvv && ok < bk)) { bvv = ov; bk = ok; }
        }

        // exp + row sum
        float s = 0.f;
#pragma unroll
        for (int i = 0; i < 8; i++) {
            float* f = (float*)&v[i];
#pragma unroll
            for (int c = 0; c < 4; c++) {
                f[c] = expf(f[c] - bvv);
                s += f[c];
            }
        }
#pragma unroll
        for (int off = 16; off; off >>= 1)
            s += __shfl_xor_sync(0xffffffffu, s, off);
        const float inv = 1.f / s;

        // accumulate soft into lane-private avg_p bins
#pragma unroll
        for (int i = 0; i < 8; i++) {
            float* f = (float*)&v[i];
#pragma unroll
            for (int c = 0; c < 4; c++) priv[i * 4 + c] += f[c] * inv;
        }

        // m output (cast to float, exact for 0..1023)
        if (lane == 0) {
            size_t mi = Z + (size_t)row;
            if (mi < (size_t)out_size) out[mi] = (float)bk;
        }
        // z_q = codebook[bk, :]  (codebook is 1 MB -> L2 resident)
        const float* cbp = &codebook[(size_t)bk * E_DIM];
        float* zo = &out[(size_t)row * E_DIM];
#pragma unroll
        for (int i = 0; i < 2; i++) {
            float4 cv = *(const float4*)&cbp[i * 128 + lane * 4];
            *(float4*)&zo[i * 128 + lane * 4] = cv;
        }
    }

    // warp-private bins -> shared (unique slots, no atomics)
#pragma unroll
    for (int i = 0; i < 8; i++)
#pragma unroll
        for (int c = 0; c < 4; c++)
            sPart[warp * K_DIM + i * 128 + lane * 4 + c] = priv[i * 4 + c];
    __syncthreads();

    // fixed-order reduce of the 8 warps -> per-CTA partial
    for (int k = tid; k < K_DIM; k += 256) {
        float sum = 0.f;
#pragma unroll
        for (int w = 0; w < 8; w++) sum += sPart[w * K_DIM + k];
        g_part[(size_t)blockIdx.x * K_DIM + k] = sum;
    }
}

// ---------------- Pass 3: diversity scalar + trailing zero ----------------
__global__ void __launch_bounds__(1024)
finalize_kernel(float* __restrict__ out, long long out_size)
{
    __shared__ double sred[32];
    const int tid = threadIdx.x; // 1024 threads, one k each
    double part = 0.0;
    {
        const int k = tid;
        float sum = 0.f;
        for (int c = 0; c < 512; c++) sum += g_part[(size_t)c * K_DIM + k];
        double avg = (double)sum / (double)B_ROWS;
        double a = avg < 1e-9 ? 1e-9 : avg;
        part = avg * (log(a) + log((double)K_DIM));
    }
#pragma unroll
    for (int off = 16; off; off >>= 1)
        part += __shfl_xor_sync(0xffffffffu, part, off);
    if ((tid & 31) == 0) sred[tid >> 5] = part;
    __syncthreads();
    if (tid < 32) {
        double v = sred[tid];
#pragma unroll
        for (int off = 16; off; off >>= 1)
            v += __shfl_xor_sync(0xffffffffu, v, off);
        if (tid == 0) {
            size_t di = (size_t)B_ROWS * E_DIM + B_ROWS;
            if ((long long)di < out_size) out[di] = (float)v;
            if ((long long)(di + 1) < out_size) out[di + 1] = 0.f;
        }
    }
}

// ---------------- launch ----------------
extern "C" void kernel_launch(void* const* d_in, const int* in_sizes, int n_in,
                              void* d_out, int out_size)
{
    const float* x       = (const float*)d_in[0]; // [B, n_in]
    const float* gumbel  = (const float*)d_in[1]; // [B, K]
    const float* W_enc   = (const float*)d_in[2]; // [K, n_in]
    const float* b_enc   = (const float*)d_in[3]; // [K]
    const float* codebook= (const float*)d_in[4]; // [K, E]
    float* out = (float*)d_out;

    dim3 g1(K_DIM / BN, B_ROWS / BM); // (8, 512)
    gemm_kernel<<<g1, 128>>>(x, W_enc, b_enc, gumbel);
    rowpass_kernel<<<512, 256>>>(codebook, out, (long long)out_size);
    finalize_kernel<<<1, 1024>>>(out, (long long)out_size);
}